// round 16
// baseline (speedup 1.0000x reference)
#include <cuda_runtime.h>
#include <cuda_fp16.h>
#include <stdint.h>

// INT2 symmetric quantized linear: y[32,14336] = x[32,4096] @ W^T
//   W[o][k] = fp16(v[o][k]-2) * scale[o/128][k]  (exact in fp16: v-2 in {-2,-1,0,1})
// => y[m][o] = sum_k fp16(x[m][k]*scale[g][k]) * (v[o][k]-2)   (scale folded into A)
//
// Inputs: x f32 [131072], packed int32 [14680064] (one byte per elem), scale f32 [458752].
// Grid 224 = (group, 64-col half), 256 threads, 2 CTAs/SM.
// 8 warps = 2 col-groups (32 cols each) x 4 kstep-subsets of each shared 256-K chunk.
// mma.sync m16n8k16, ldmatrix A(xs), raw-word dequant B, cp.async pw, 4-way K-reduction.

#define IN_F   4096
#define OUT_F  14336
#define GS     128
#define NCTAS  224
#define CKR    256                  // K per chunk
#define NCH    16                   // chunks

#define XS_STRIDE 528               // 512B fp16 + 16 pad
#define XSBUF (32 * XS_STRIDE)      // 16896
#define PWR_STRIDE 272              // 256B raw int32 + 16 pad
#define PWRBUF (64 * PWR_STRIDE)    // 17408 (64 weight rows per CTA)

#define SM_SCALE 0                  // 16384 B fp32 scales
#define SM_XS    16384              // 2 bufs
#define SM_PWR   (16384 + 2 * XSBUF)        // 50176 ; 2 bufs
#define SM_TOTAL (SM_PWR + 2 * PWRBUF)      // 84992
#define RSTRIDE  68                 // reduction scratch row stride (floats)
#define RREGION  (32 * RSTRIDE * 4) // 8704 B per partial region

__device__ __forceinline__ uint32_t smem_u32(const void* p) {
    uint32_t a;
    asm("{ .reg .u64 t; cvta.to.shared.u64 t, %1; cvt.u32.u64 %0, t; }" : "=r"(a) : "l"(p));
    return a;
}
__device__ __forceinline__ uint32_t hsub2u(uint32_t a, uint32_t b) {
    uint32_t d; asm("sub.rn.f16x2 %0, %1, %2;" : "=r"(d) : "r"(a), "r"(b)); return d;
}
// nib = two 2-bit weights (pre-masked). fp16x2 of (v0-2, v1-2), exact.
__device__ __forceinline__ uint32_t deq_nib(uint32_t nib) {
    uint32_t u = nib * 0x4001u, r;
    asm("lop3.b32 %0, %1, %2, %3, 0xEA;" : "=r"(r)
        : "r"(u), "r"(0x00030003u), "r"(0x64006400u));
    return hsub2u(r, 0x64026402u);
}

#define LDSM_X4(R, ADDR) \
    asm volatile("ldmatrix.sync.aligned.m8n8.x4.shared.b16 {%0,%1,%2,%3}, [%4];" \
        : "=r"((R)[0]), "=r"((R)[1]), "=r"((R)[2]), "=r"((R)[3]) : "r"(ADDR))

#define MMA16816(C, A, B0, B1) \
    asm volatile("mma.sync.aligned.m16n8k16.row.col.f32.f16.f16.f32 " \
        "{%0,%1,%2,%3}, {%4,%5,%6,%7}, {%8,%9}, {%0,%1,%2,%3};" \
        : "+f"((C)[0]), "+f"((C)[1]), "+f"((C)[2]), "+f"((C)[3]) \
        : "r"((A)[0]), "r"((A)[1]), "r"((A)[2]), "r"((A)[3]), "r"(B0), "r"(B1))

#define STS128(ADDR, R0, R1, R2, R3) \
    asm volatile("st.shared.v4.b32 [%0], {%1, %2, %3, %4};" \
        :: "r"(ADDR), "r"(R0), "r"(R1), "r"(R2), "r"(R3) : "memory")

#define LDS32(DST, ADDR) \
    asm volatile("ld.shared.u32 %0, [%1];" : "=r"(DST) : "r"(ADDR))

#define LDS128F(ADDR, V) \
    asm volatile("ld.shared.v4.f32 {%0,%1,%2,%3}, [%4];" \
        : "=f"((V).x), "=f"((V).y), "=f"((V).z), "=f"((V).w) : "r"(ADDR))

#define CP_ASYNC16(SADDR, GADDR) \
    asm volatile("cp.async.cg.shared.global [%0], [%1], 16;" :: "r"(SADDR), "l"(GADDR))

__global__ void __launch_bounds__(256, 2)
int2_linear_kernel(const float* __restrict__ x,
                   const int* __restrict__ pw,     // one packed byte per int32
                   const float* __restrict__ scale,
                   float* __restrict__ out)
{
    extern __shared__ char smem[];
    const int tid  = threadIdx.x;
    const int warp = tid >> 5;
    const int lane = tid & 31;
    const int g    = blockIdx.x >> 1;      // weight group
    const int h    = blockIdx.x & 1;       // 64-col half of the group
    const uint32_t sbase = smem_u32(smem);

    const int colgrp = warp & 1;           // 32-col group within the half
    const int ksub   = warp >> 1;          // kstep subset 0..3
    const int ncb    = colgrp * 32;

    // ---- stage scales: 4096 fp32 = 16KB ----
    {
        const uint4* sg = reinterpret_cast<const uint4*>(scale + (size_t)g * IN_F);
        uint4* ss = reinterpret_cast<uint4*>(smem + SM_SCALE);
#pragma unroll
        for (int i = 0; i < 4; ++i) ss[tid + i * 256] = sg[tid + i * 256];
    }

    // ---- staging roles ----
    const int* pwg = pw + (size_t)(g * GS + h * 64) * (IN_F / 4);  // 64 rows x 1024 words
    const int prow = tid >> 2, pq = tid & 3;       // pw: 4 thr/row, 16 int32 each
    const int xrow = tid >> 3, xseg = tid & 7;     // x: 32 rows x 8 segs of 32 k

#define CPW(C) do {                                                            \
    uint32_t dst = sbase + SM_PWR + ((C) & 1) * PWRBUF                         \
                 + prow * PWR_STRIDE + pq * 64;                                \
    const int* src = pwg + (size_t)prow * 1024 + (C) * 64 + pq * 16;           \
    _Pragma("unroll")                                                          \
    for (int u = 0; u < 4; ++u) CP_ASYNC16(dst + u * 16, src + u * 4);         \
} while (0)

    float4 F[8];   // x staging regs (32 floats)
#define XLDG(C) do {                                                           \
    const float* xg = x + (size_t)xrow * IN_F + (C) * CKR + xseg * 8;          \
    _Pragma("unroll")                                                          \
    for (int i = 0; i < 4; ++i) {                                              \
        F[2 * i]     = *reinterpret_cast<const float4*>(xg + i * 64);          \
        F[2 * i + 1] = *reinterpret_cast<const float4*>(xg + i * 64 + 4);      \
    }                                                                          \
} while (0)

#define XSTS(C) do {                                                           \
    uint32_t sa = sbase + SM_SCALE + (uint32_t)(((C) * CKR + xseg * 8) * 4);   \
    uint32_t xa = sbase + SM_XS + ((C) & 1) * XSBUF                            \
                + xrow * XS_STRIDE + xseg * 16;                                \
    _Pragma("unroll")                                                          \
    for (int i = 0; i < 4; ++i) {                                              \
        float4 s0, s1;                                                         \
        LDS128F(sa + i * 256, s0);                                             \
        LDS128F(sa + i * 256 + 16, s1);                                        \
        float4 v0 = F[2 * i], v1 = F[2 * i + 1];                               \
        __half2 h0 = __floats2half2_rn(v0.x * s0.x, v0.y * s0.y);              \
        __half2 h1 = __floats2half2_rn(v0.z * s0.z, v0.w * s0.w);              \
        __half2 h2 = __floats2half2_rn(v1.x * s1.x, v1.y * s1.y);              \
        __half2 h3 = __floats2half2_rn(v1.z * s1.z, v1.w * s1.w);              \
        STS128(xa + i * 128,                                                   \
               *reinterpret_cast<uint32_t*>(&h0),                              \
               *reinterpret_cast<uint32_t*>(&h1),                              \
               *reinterpret_cast<uint32_t*>(&h2),                              \
               *reinterpret_cast<uint32_t*>(&h3));                             \
    }                                                                          \
} while (0)

    // ---- prologue ----
    CPW(0);
    asm volatile("cp.async.commit_group;" ::: "memory");
    XLDG(0);
    asm volatile("cp.async.wait_group 0;" ::: "memory");
    __syncthreads();                 // scales + pw buf0 visible
    XSTS(0);
    __syncthreads();                 // xs buf0 visible

    // ---- per-warp fragment addressing (R14-proven maps) ----
    const int q = lane & 3;
    const uint32_t sh = (uint32_t)((q & 1) * 4);
    const uint32_t wsel = (uint32_t)((q >> 1) * 4);
    uint32_t pkoff[4];
#pragma unroll
    for (int t = 0; t < 4; ++t)
        pkoff[t] = (uint32_t)((ncb + t * 8 + (lane >> 2)) * PWR_STRIDE) + wsel;
    const int arow = (lane & 7) + ((lane >> 3) & 1) * 8;
    const uint32_t acol = ((lane >> 4) & 1) * 16;
    const uint32_t amoff = (uint32_t)(arow * XS_STRIDE) + acol + (uint32_t)(ksub * 4) * 32;
    const uint32_t pkjoff = (uint32_t)(ksub * 4) * 16;

    float c[2][4][4] = {};    // [m-tile][n-octet][frag]

    for (int r = 0; r < NCH; ++r) {
        const int par = r & 1;

        if (r + 1 < NCH) {
            CPW(r + 1);
            asm volatile("cp.async.commit_group;" ::: "memory");
            XLDG(r + 1);
        }

        const uint32_t pkb = sbase + SM_PWR + par * PWRBUF + pkjoff;
        const uint32_t am0 = sbase + SM_XS + par * XSBUF + amoff;
        const uint32_t am1 = am0 + 16 * XS_STRIDE;

#pragma unroll
        for (int jj = 0; jj < 4; ++jj) {      // this warp's 4 ksteps of the chunk
            uint32_t a0[4], a1[4];
            LDSM_X4(a0, am0 + jj * 32);
            LDSM_X4(a1, am1 + jj * 32);
#pragma unroll
            for (int t = 0; t < 4; ++t) {
                uint32_t r0, r1;
                LDS32(r0, pkb + pkoff[t] + jj * 16);
                LDS32(r1, pkb + pkoff[t] + jj * 16 + 8);
                uint32_t b0 = deq_nib((r0 >> sh) & 0xFu);
                uint32_t b1 = deq_nib((r1 >> sh) & 0xFu);
                MMA16816(c[0][t], a0, b0, b1);
                MMA16816(c[1][t], a1, b0, b1);
            }
        }

        if (r + 1 < NCH) {
            XSTS(r + 1);
            asm volatile("cp.async.wait_group 0;" ::: "memory");
        }
        __syncthreads();
    }

    // ---- 4-way K reduction (scratch reuses xs area) ----
    const uint32_t red = sbase + SM_XS;
    if (ksub != 0) {
        const uint32_t reg = red + (uint32_t)(ksub - 1) * RREGION;
#pragma unroll
        for (int mt = 0; mt < 2; ++mt) {
#pragma unroll
            for (int t = 0; t < 4; ++t) {
                const int m = mt * 16 + (lane >> 2);
                const int n = ncb + t * 8 + q * 2;
                uint32_t p0 = reg + (uint32_t)((m * RSTRIDE + n) * 4);
                uint32_t p1 = reg + (uint32_t)(((m + 8) * RSTRIDE + n) * 4);
                asm volatile("st.shared.v2.f32 [%0], {%1, %2};"
                             :: "r"(p0), "f"(c[mt][t][0]), "f"(c[mt][t][1]) : "memory");
                asm volatile("st.shared.v2.f32 [%0], {%1, %2};"
                             :: "r"(p1), "f"(c[mt][t][2]), "f"(c[mt][t][3]) : "memory");
            }
        }
    }
    __syncthreads();
    if (ksub == 0) {
#pragma unroll
        for (int mt = 0; mt < 2; ++mt) {
#pragma unroll
            for (int t = 0; t < 4; ++t) {
                const int m = mt * 16 + (lane >> 2);
                const int n = ncb + t * 8 + q * 2;
                float acc0 = c[mt][t][0], acc1 = c[mt][t][1];
                float acc2 = c[mt][t][2], acc3 = c[mt][t][3];
#pragma unroll
                for (int s = 0; s < 3; ++s) {
                    const uint32_t reg = red + (uint32_t)s * RREGION;
                    uint32_t p0 = reg + (uint32_t)((m * RSTRIDE + n) * 4);
                    uint32_t p1 = reg + (uint32_t)(((m + 8) * RSTRIDE + n) * 4);
                    float e0, e1, e2, e3;
                    asm volatile("ld.shared.v2.f32 {%0, %1}, [%2];" : "=f"(e0), "=f"(e1) : "r"(p0));
                    asm volatile("ld.shared.v2.f32 {%0, %1}, [%2];" : "=f"(e2), "=f"(e3) : "r"(p1));
                    acc0 += e0; acc1 += e1; acc2 += e2; acc3 += e3;
                }
                const int col = g * GS + h * 64 + n;
                *reinterpret_cast<float2*>(out + (size_t)m * OUT_F + col) =
                    make_float2(acc0, acc1);
                *reinterpret_cast<float2*>(out + (size_t)(m + 8) * OUT_F + col) =
                    make_float2(acc2, acc3);
            }
        }
    }
}

extern "C" void kernel_launch(void* const* d_in, const int* in_sizes, int n_in,
                              void* d_out, int out_size) {
    // Identify inputs by element count: x 131072, packed 14680064, scale 458752
    const float* x  = 0;
    const int*   pw = 0;
    const float* sc = 0;
    for (int i = 0; i < n_in; ++i) {
        if      (in_sizes[i] == 131072)   x  = (const float*)d_in[i];
        else if (in_sizes[i] == 14680064) pw = (const int*)d_in[i];
        else if (in_sizes[i] == 458752)   sc = (const float*)d_in[i];
    }
    float* out = (float*)d_out;
    (void)out_size;

    cudaFuncSetAttribute(int2_linear_kernel,
                         cudaFuncAttributeMaxDynamicSharedMemorySize, SM_TOTAL);
    int2_linear_kernel<<<NCTAS, 256, SM_TOTAL>>>(x, pw, sc, out);
}